// round 11
// baseline (speedup 1.0000x reference)
#include <cuda_runtime.h>

// out[b, s, d] = x[b, s, d] - sum_d' x[b, s, d']
// x: (8, 8192, 512) fp32 -> 65536 rows of 512 floats.
// Converged memory scheme (warp-per-row, float4, streaming hints): measured
// DRAM ceiling ~5.9 TB/s; kernel time pinned at the compulsory-traffic floor.
// R9: CTA-granularity tune only — 1024-thread CTAs / 2048 blocks (fewer
// waves, less dispatch + wave-transition overhead). 256t->45.0, 512t->43.5,
// extrapolating one step.

static constexpr int D = 512;
static constexpr int VEC_PER_ROW = D / 4;              // 128 float4 per row
static constexpr int VEC_PER_LANE = VEC_PER_ROW / 32;  // 4

__global__ void __launch_bounds__(1024)
row_center_kernel(const float4* __restrict__ x, float4* __restrict__ out) {
    const int warp_global = (blockIdx.x * blockDim.x + threadIdx.x) >> 5;
    const int lane = threadIdx.x & 31;

    const float4* __restrict__ row = x + (size_t)warp_global * VEC_PER_ROW;
    float4* __restrict__ orow = out + (size_t)warp_global * VEC_PER_ROW;

    float4 v[VEC_PER_LANE];
    float s = 0.0f;
#pragma unroll
    for (int i = 0; i < VEC_PER_LANE; i++) {
        v[i] = __ldcs(&row[lane + 32 * i]);
        s += (v[i].x + v[i].y) + (v[i].z + v[i].w);
    }

    // warp tree reduction
#pragma unroll
    for (int off = 16; off > 0; off >>= 1)
        s += __shfl_xor_sync(0xffffffffu, s, off);

#pragma unroll
    for (int i = 0; i < VEC_PER_LANE; i++) {
        float4 r = v[i];
        r.x -= s; r.y -= s; r.z -= s; r.w -= s;
        __stcs(&orow[lane + 32 * i], r);
    }
}

extern "C" void kernel_launch(void* const* d_in, const int* in_sizes, int n_in,
                              void* d_out, int out_size) {
    const float* x = (const float*)d_in[0];
    float* out = (float*)d_out;
    const int n_rows = in_sizes[0] / D;          // 65536
    const int threads = 1024;                    // 32 warps/block
    const int blocks = n_rows / (threads / 32);  // 2048, exact

    row_center_kernel<<<blocks, threads>>>(
        (const float4*)x, (float4*)out);
}